// round 13
// baseline (speedup 1.0000x reference)
#include <cuda_runtime.h>
#include <cuda_fp16.h>
#include <stdint.h>

// Problem constants (fixed by the dataset)
#define N_NODES 50000
#define N_EDGES 800000
#define D_FEAT  128
#define HIDDEN  128

// Single-block scan geometry
#define ST 1024
#define SCHUNK ((N_NODES + ST - 1) / ST)   // 49

// Scratch (static device globals — no allocation allowed)
__device__ float  g_dinv[N_NODES];
__device__ __half g_h1h[(size_t)N_NODES * HIDDEN];    // x @ W1 (fp16)
__device__ float  g_h2 [N_NODES];                     // relu(.) @ W2 per node
__device__ int    g_cnt   [N_NODES];                  // in-degree (no self loop)
__device__ int    g_cursor[N_NODES];
__device__ int    g_row   [N_NODES];                  // CSR row starts
__device__ int2   g_csr   [N_EDGES];                  // packed {src, norm-bits}
__device__ int    g_is64;

// ---------------------------------------------------------------------------
// Edge fetch helper (dtype decided by runtime probe)
// ---------------------------------------------------------------------------
__device__ __forceinline__ void load_edge(const void* ei, int i, int& s, int& d) {
    if (g_is64) {
        const long long* p = (const long long*)ei;
        s = (int)p[i];
        d = (int)p[i + N_EDGES];
    } else {
        const int* p = (const int*)ei;
        s = p[i];
        d = p[i + N_EDGES];
    }
    s = min(max(s, 0), N_NODES - 1);
    d = min(max(d, 0), N_NODES - 1);
}

// ---------------------------------------------------------------------------
// K_prep: zero counters; thread 0 probes edge dtype.
// ---------------------------------------------------------------------------
__global__ void k_prep(const void* __restrict__ ei) {
    int i = blockIdx.x * blockDim.x + threadIdx.x;
    if (i < N_NODES) { g_cnt[i] = 0; g_cursor[i] = 0; }
    if (i == 0) {
        const long long* p = (const long long*)ei;
        int ok64 = 1;
        for (int k = 0; k < 16; k++) {
            long long v = p[k];
            if (v < 0 || v >= N_NODES) { ok64 = 0; break; }
        }
        g_is64 = ok64;
    }
}

// ---------------------------------------------------------------------------
// K_count: in-degree counts straight from edge_index
// ---------------------------------------------------------------------------
__global__ void k_count(const void* __restrict__ ei) {
    int i = blockIdx.x * blockDim.x + threadIdx.x;
    if (i < N_EDGES) {
        int s, d;
        load_edge(ei, i, s, d);
        atomicAdd(&g_cnt[d], 1);
    }
}

// ---------------------------------------------------------------------------
// K_scan: ONE block, 1024 threads. Thread t owns nodes [t*49, (t+1)*49).
// Pass 1: local sum. Block scan of 1024 partials. Pass 2: write exclusive
// prefixes to g_row; also dinv = rsqrt(1+cnt). No cross-block sync needed.
// ---------------------------------------------------------------------------
__global__ __launch_bounds__(ST) void k_scan() {
    __shared__ int sh[ST];
    const int t = threadIdx.x;
    const int lo = t * SCHUNK;
    const int hi = min(lo + SCHUNK, N_NODES);

    int local = 0;
    for (int i = lo; i < hi; i++) local += g_cnt[i];
    sh[t] = local;
    __syncthreads();

    // Hillis-Steele inclusive scan over 1024 partials
    for (int off = 1; off < ST; off <<= 1) {
        int v = (t >= off) ? sh[t - off] : 0;
        __syncthreads();
        sh[t] += v;
        __syncthreads();
    }
    int base = sh[t] - local;   // exclusive prefix for this thread's chunk

    for (int i = lo; i < hi; i++) {
        int c = g_cnt[i];
        g_row[i]  = base;
        g_dinv[i] = rsqrtf((float)(1 + c));
        base += c;
    }
}

// ---------------------------------------------------------------------------
// K_fill: place edges into CSR slots; packed {src, norm}
// ---------------------------------------------------------------------------
__global__ void k_fill(const void* __restrict__ ei) {
    int e = blockIdx.x * blockDim.x + threadIdx.x;
    if (e < N_EDGES) {
        int src, dst;
        load_edge(ei, e, src, dst);
        int pos = atomicAdd(&g_cursor[dst], 1);
        float norm = g_dinv[src] * g_dinv[dst];
        g_csr[g_row[dst] + pos] = make_int2(src, __float_as_int(norm));
    }
}

// ---------------------------------------------------------------------------
// K3: h1 = x @ W1.  BM=128, BN=128, BK=8, 256 threads, 8x8 per-thread tile.
// Epilogue writes fp16 only. Runs on a forked stream, overlapped with CSR build.
// ---------------------------------------------------------------------------
#define BM 128
#define BN 128
#define BK 8

__global__ __launch_bounds__(256) void k_gemm1(const float* __restrict__ x,
                                               const float* __restrict__ W) {
    __shared__ float As[BK][BM];
    __shared__ float Bs[BK][BN];

    const int tid = threadIdx.x;
    const int blockRow = blockIdx.x * BM;
    const int rowBase = (tid >> 4) * 8;
    const int colBase = (tid & 15) * 8;

    float acc[8][8];
#pragma unroll
    for (int i = 0; i < 8; i++)
#pragma unroll
        for (int j = 0; j < 8; j++) acc[i][j] = 0.0f;

    for (int k0 = 0; k0 < D_FEAT; k0 += BK) {
        {
            int r  = tid >> 1;
            int kv = (tid & 1) * 4;
            int gr = blockRow + r;
            float4 v = make_float4(0.f, 0.f, 0.f, 0.f);
            if (gr < N_NODES)
                v = *(const float4*)(x + (size_t)gr * D_FEAT + k0 + kv);
            As[kv + 0][r] = v.x;
            As[kv + 1][r] = v.y;
            As[kv + 2][r] = v.z;
            As[kv + 3][r] = v.w;
        }
        {
            int k  = tid >> 5;
            int c4 = (tid & 31) * 4;
            *(float4*)(&Bs[k][c4]) = *(const float4*)(W + (size_t)(k0 + k) * HIDDEN + c4);
        }
        __syncthreads();

#pragma unroll
        for (int kk = 0; kk < BK; kk++) {
            float4 a0 = *(float4*)(&As[kk][rowBase]);
            float4 a1 = *(float4*)(&As[kk][rowBase + 4]);
            float4 b0 = *(float4*)(&Bs[kk][colBase]);
            float4 b1 = *(float4*)(&Bs[kk][colBase + 4]);
            float a[8] = {a0.x, a0.y, a0.z, a0.w, a1.x, a1.y, a1.z, a1.w};
            float b[8] = {b0.x, b0.y, b0.z, b0.w, b1.x, b1.y, b1.z, b1.w};
#pragma unroll
            for (int i = 0; i < 8; i++)
#pragma unroll
                for (int j = 0; j < 8; j++)
                    acc[i][j] = fmaf(a[i], b[j], acc[i][j]);
        }
        __syncthreads();
    }

#pragma unroll
    for (int i = 0; i < 8; i++) {
        int gr = blockRow + rowBase + i;
        if (gr < N_NODES) {
            __half2 hpack[4];
            hpack[0] = __floats2half2_rn(acc[i][0], acc[i][1]);
            hpack[1] = __floats2half2_rn(acc[i][2], acc[i][3]);
            hpack[2] = __floats2half2_rn(acc[i][4], acc[i][5]);
            hpack[3] = __floats2half2_rn(acc[i][6], acc[i][7]);
            *(uint4*)(g_h1h + (size_t)gr * HIDDEN + colBase) = *(uint4*)hpack;
        }
    }
}

// ---------------------------------------------------------------------------
// Macro: accumulate one fp16 row (uint4 = 8 halves) scaled by n into a[8]
// ---------------------------------------------------------------------------
#define ACC_ROW(r_, n_)                                                        \
    do {                                                                       \
        float2 f_;                                                             \
        f_ = __half22float2(*(__half2*)&(r_).x);                               \
        a[0] = fmaf(f_.x, (n_), a[0]); a[1] = fmaf(f_.y, (n_), a[1]);          \
        f_ = __half22float2(*(__half2*)&(r_).y);                               \
        a[2] = fmaf(f_.x, (n_), a[2]); a[3] = fmaf(f_.y, (n_), a[3]);          \
        f_ = __half22float2(*(__half2*)&(r_).z);                               \
        a[4] = fmaf(f_.x, (n_), a[4]); a[5] = fmaf(f_.y, (n_), a[5]);          \
        f_ = __half22float2(*(__half2*)&(r_).w);                               \
        a[6] = fmaf(f_.x, (n_), a[6]); a[7] = fmaf(f_.y, (n_), a[7]);          \
    } while (0)

#define GATHER2(off_)                                                          \
    do {                                                                       \
        int2 e_ = g_csr[i + (off_) + half];                                    \
        uint4 r_ = *(const uint4*)(g_h1h + (size_t)e_.x * HIDDEN + colOff);    \
        float n_ = __int_as_float(e_.y);                                       \
        ACC_ROW(r_, n_);                                                       \
    } while (0)

// ---------------------------------------------------------------------------
// K_agg1: fused layer-1 aggregation + epilogue. One warp per node,
// 2 edges per slot (half-warps), 16-edge unroll = 8 LDG.128 in flight/lane.
// ---------------------------------------------------------------------------
__global__ __launch_bounds__(256) void k_agg1(const float* __restrict__ b1,
                                              const float* __restrict__ W2,
                                              const float* __restrict__ b2,
                                              float* __restrict__ out) {
    int node = (blockIdx.x * blockDim.x + threadIdx.x) >> 5;
    int lane = threadIdx.x & 31;
    if (node >= N_NODES) return;

    const int half = lane >> 4;              // 0 or 1
    const int l16  = lane & 15;              // 0..15
    const size_t colOff = (size_t)l16 * 8;   // 8 halves per lane

    int beg = g_row[node];
    int end = beg + g_cnt[node];

    float a[8];
#pragma unroll
    for (int r = 0; r < 8; r++) a[r] = 0.f;

    int i = beg;
    for (; i + 15 < end; i += 16) {
        GATHER2(0); GATHER2(2); GATHER2(4); GATHER2(6);
        GATHER2(8); GATHER2(10); GATHER2(12); GATHER2(14);
    }
    for (; i + 7 < end; i += 8) {
        GATHER2(0); GATHER2(2); GATHER2(4); GATHER2(6);
    }
    for (; i + 3 < end; i += 4) {
        GATHER2(0); GATHER2(2);
    }
    for (; i + 1 < end; i += 2) {
        GATHER2(0);
    }
    if (i < end && half == 0) {
        int2 e0 = g_csr[i];
        uint4 r0 = *(const uint4*)(g_h1h + (size_t)e0.x * HIDDEN + colOff);
        float n0 = __int_as_float(e0.y);
        ACC_ROW(r0, n0);
    }

    // fold the two half-warps
#pragma unroll
    for (int r = 0; r < 8; r++)
        a[r] += __shfl_xor_sync(0xFFFFFFFFu, a[r], 16);

    float di = g_dinv[node];
    float d2 = di * di;

    uint4 sr = *(const uint4*)(g_h1h + (size_t)node * HIDDEN + colOff);
    float s[8];
    {
        float2 f;
        f = __half22float2(*(__half2*)&sr.x); s[0] = f.x; s[1] = f.y;
        f = __half22float2(*(__half2*)&sr.y); s[2] = f.x; s[3] = f.y;
        f = __half22float2(*(__half2*)&sr.z); s[4] = f.x; s[5] = f.y;
        f = __half22float2(*(__half2*)&sr.w); s[6] = f.x; s[7] = f.y;
    }
    float4 bb0 = *(const float4*)(b1 + colOff);
    float4 bb1 = *(const float4*)(b1 + colOff + 4);
    float4 w0  = *(const float4*)(W2 + colOff);
    float4 w1  = *(const float4*)(W2 + colOff + 4);
    float bbv[8] = {bb0.x, bb0.y, bb0.z, bb0.w, bb1.x, bb1.y, bb1.z, bb1.w};
    float wv [8] = {w0.x,  w0.y,  w0.z,  w0.w,  w1.x,  w1.y,  w1.z,  w1.w};

    float sum = 0.f;
#pragma unroll
    for (int r = 0; r < 8; r++) {
        float t = fmaxf(fmaf(s[r], d2, a[r]) + bbv[r], 0.0f);
        sum = fmaf(t, wv[r], sum);
    }
#pragma unroll
    for (int off = 8; off > 0; off >>= 1)
        sum += __shfl_xor_sync(0xFFFFFFFFu, sum, off);

    if (lane == 0) {
        g_h2[node] = sum;
        out[node]  = fmaf(sum, d2, b2[0]);  // layer-2 self-loop + bias
    }
}

// ---------------------------------------------------------------------------
// K_agg2: layer-2 gather. 8 lanes per node (4 nodes per warp).
// ---------------------------------------------------------------------------
__global__ __launch_bounds__(256) void k_agg2(float* __restrict__ out) {
    int gwarp = (blockIdx.x * blockDim.x + threadIdx.x) >> 5;
    int lane  = threadIdx.x & 31;
    int sub   = lane >> 3;     // 0..3
    int l8    = lane & 7;      // 0..7
    int node  = gwarp * 4 + sub;
    if (node >= N_NODES) return;

    int beg = g_row[node];
    int end = beg + g_cnt[node];

    float sum = 0.f;
    for (int i = beg + l8; i < end; i += 8) {
        int2 e = g_csr[i];
        sum = fmaf(g_h2[e.x], __int_as_float(e.y), sum);
    }

#pragma unroll
    for (int off = 4; off > 0; off >>= 1)
        sum += __shfl_xor_sync(0xFFFFFFFFu, sum, off);

    if (l8 == 0) out[node] += sum;
}

// ---------------------------------------------------------------------------
// Launch. GEMM on a forked side stream overlaps the CSR build chain.
// No grid barriers anywhere — all cross-block ordering via kernel boundaries.
// ---------------------------------------------------------------------------
extern "C" void kernel_launch(void* const* d_in, const int* in_sizes, int n_in,
                              void* d_out, int out_size) {
    const float* x  = (const float*)d_in[0];
    const void*  ei = d_in[1];
    const float* W1 = (const float*)d_in[2];
    const float* b1 = (const float*)d_in[3];
    const float* W2 = (const float*)d_in[4];
    const float* b2 = (const float*)d_in[5];
    float*       out = (float*)d_out;

    static cudaStream_t s2 = nullptr;
    static cudaEvent_t  evFork = nullptr, evJoin = nullptr;
    if (s2 == nullptr) {
        cudaStreamCreateWithFlags(&s2, cudaStreamNonBlocking);
        cudaEventCreateWithFlags(&evFork, cudaEventDisableTiming);
        cudaEventCreateWithFlags(&evJoin, cudaEventDisableTiming);
    }

    const int T = 256;

    // Fork: GEMM on side stream (depends only on x, W1)
    cudaEventRecord(evFork, 0);
    cudaStreamWaitEvent(s2, evFork, 0);
    k_gemm1<<<(N_NODES + BM - 1) / BM, 256, 0, s2>>>(x, W1);
    cudaEventRecord(evJoin, s2);

    // CSR build chain on main stream
    k_prep <<<(N_NODES + T - 1) / T, T>>>(ei);
    k_count<<<(N_EDGES + T - 1) / T, T>>>(ei);
    k_scan <<<1, ST>>>();
    k_fill <<<(N_EDGES + T - 1) / T, T>>>(ei);

    // Join: aggregation needs both CSR and h1
    cudaStreamWaitEvent(0, evJoin, 0);
    {
        long long blocks = ((long long)N_NODES * 32 + T - 1) / T;
        k_agg1<<<(unsigned)blocks, T>>>(b1, W2, b2, out);
    }
    {
        long long blocks = ((long long)N_NODES * 8 + T - 1) / T;
        k_agg2<<<(unsigned)blocks, T>>>(out);
    }
}

// round 14
// speedup vs baseline: 1.6732x; 1.6732x over previous
#include <cuda_runtime.h>
#include <cuda_fp16.h>
#include <stdint.h>

// Problem constants (fixed by the dataset)
#define N_NODES 50000
#define N_EDGES 800000
#define D_FEAT  128
#define HIDDEN  128

#define SCAN_T   256
#define SCAN_B   ((N_NODES + SCAN_T - 1) / SCAN_T)   // 196

// Scratch (static device globals — no allocation allowed)
__device__ float  g_dinv[N_NODES];
__device__ __half g_h1h[(size_t)N_NODES * HIDDEN];    // x @ W1 (fp16)
__device__ float  g_h2 [N_NODES];                     // relu(.) @ W2 per node
__device__ int    g_cnt   [N_NODES];                  // in-degree (no self loop)
__device__ int    g_cursor[N_NODES];
__device__ int    g_row   [N_NODES];                  // CSR row starts
__device__ int    g_bsum  [SCAN_B];
__device__ int2   g_csr   [N_EDGES];                  // packed {src, norm-bits}
__device__ int    g_is64;

// ---------------------------------------------------------------------------
// Edge fetch helper (dtype decided by runtime probe)
// ---------------------------------------------------------------------------
__device__ __forceinline__ void load_edge(const void* ei, int i, int& s, int& d) {
    if (g_is64) {
        const long long* p = (const long long*)ei;
        s = (int)p[i];
        d = (int)p[i + N_EDGES];
    } else {
        const int* p = (const int*)ei;
        s = p[i];
        d = p[i + N_EDGES];
    }
    s = min(max(s, 0), N_NODES - 1);
    d = min(max(d, 0), N_NODES - 1);
}

// ---------------------------------------------------------------------------
// K_prep: zero counters; thread 0 probes edge dtype.
// ---------------------------------------------------------------------------
__global__ void k_prep(const void* __restrict__ ei) {
    int i = blockIdx.x * blockDim.x + threadIdx.x;
    if (i < N_NODES) { g_cnt[i] = 0; g_cursor[i] = 0; }
    if (i == 0) {
        const long long* p = (const long long*)ei;
        int ok64 = 1;
        for (int k = 0; k < 16; k++) {
            long long v = p[k];
            if (v < 0 || v >= N_NODES) { ok64 = 0; break; }
        }
        g_is64 = ok64;
    }
}

// ---------------------------------------------------------------------------
// K_count: in-degree counts straight from edge_index
// ---------------------------------------------------------------------------
__global__ void k_count(const void* __restrict__ ei) {
    int i = blockIdx.x * blockDim.x + threadIdx.x;
    if (i < N_EDGES) {
        int s, d;
        load_edge(ei, i, s, d);
        atomicAdd(&g_cnt[d], 1);
    }
}

// ---------------------------------------------------------------------------
// Scan step 1: per-block sums of g_cnt; also dinv = rsqrt(1+cnt) (fused)
// (coalesced, fully parallel — measured 5.2us in R8)
// ---------------------------------------------------------------------------
__global__ void k_scan1() {
    __shared__ int sh[SCAN_T];
    int i = blockIdx.x * SCAN_T + threadIdx.x;
    int c = (i < N_NODES) ? g_cnt[i] : 0;
    if (i < N_NODES) g_dinv[i] = rsqrtf((float)(1 + c));
    sh[threadIdx.x] = c;
    __syncthreads();
    for (int s = SCAN_T / 2; s > 0; s >>= 1) {
        if (threadIdx.x < s) sh[threadIdx.x] += sh[threadIdx.x + s];
        __syncthreads();
    }
    if (threadIdx.x == 0) g_bsum[blockIdx.x] = sh[0];
}

// ---------------------------------------------------------------------------
// Scan step 2 (fused): every block redundantly scans the 196 block sums,
// then its local 256-element exclusive scan -> g_row. (measured 5.5us in R8)
// ---------------------------------------------------------------------------
__global__ void k_scan3() {
    __shared__ int shb[SCAN_T];
    __shared__ int sh [SCAN_T];

    int bv = (threadIdx.x < SCAN_B) ? g_bsum[threadIdx.x] : 0;
    shb[threadIdx.x] = bv;
    __syncthreads();
    for (int off = 1; off < SCAN_T; off <<= 1) {
        int t = (threadIdx.x >= off) ? shb[threadIdx.x - off] : 0;
        __syncthreads();
        shb[threadIdx.x] += t;
        __syncthreads();
    }
    int blockOff = shb[blockIdx.x] - g_bsum[blockIdx.x];

    int i = blockIdx.x * SCAN_T + threadIdx.x;
    int v = (i < N_NODES) ? g_cnt[i] : 0;
    sh[threadIdx.x] = v;
    __syncthreads();
    for (int off = 1; off < SCAN_T; off <<= 1) {
        int t = (threadIdx.x >= off) ? sh[threadIdx.x - off] : 0;
        __syncthreads();
        sh[threadIdx.x] += t;
        __syncthreads();
    }
    if (i < N_NODES)
        g_row[i] = blockOff + sh[threadIdx.x] - v;
}

// ---------------------------------------------------------------------------
// K_fill: place edges into CSR slots; packed {src, norm}
// ---------------------------------------------------------------------------
__global__ void k_fill(const void* __restrict__ ei) {
    int e = blockIdx.x * blockDim.x + threadIdx.x;
    if (e < N_EDGES) {
        int src, dst;
        load_edge(ei, e, src, dst);
        int pos = atomicAdd(&g_cursor[dst], 1);
        float norm = g_dinv[src] * g_dinv[dst];
        g_csr[g_row[dst] + pos] = make_int2(src, __float_as_int(norm));
    }
}

// ---------------------------------------------------------------------------
// K3: h1 = x @ W1.  BM=128, BN=128, BK=8, 256 threads, 8x8 per-thread tile.
// Epilogue writes fp16 only. Runs on a forked stream, overlapped with CSR build.
// ---------------------------------------------------------------------------
#define BM 128
#define BN 128
#define BK 8

__global__ __launch_bounds__(256) void k_gemm1(const float* __restrict__ x,
                                               const float* __restrict__ W) {
    __shared__ float As[BK][BM];
    __shared__ float Bs[BK][BN];

    const int tid = threadIdx.x;
    const int blockRow = blockIdx.x * BM;
    const int rowBase = (tid >> 4) * 8;
    const int colBase = (tid & 15) * 8;

    float acc[8][8];
#pragma unroll
    for (int i = 0; i < 8; i++)
#pragma unroll
        for (int j = 0; j < 8; j++) acc[i][j] = 0.0f;

    for (int k0 = 0; k0 < D_FEAT; k0 += BK) {
        {
            int r  = tid >> 1;
            int kv = (tid & 1) * 4;
            int gr = blockRow + r;
            float4 v = make_float4(0.f, 0.f, 0.f, 0.f);
            if (gr < N_NODES)
                v = *(const float4*)(x + (size_t)gr * D_FEAT + k0 + kv);
            As[kv + 0][r] = v.x;
            As[kv + 1][r] = v.y;
            As[kv + 2][r] = v.z;
            As[kv + 3][r] = v.w;
        }
        {
            int k  = tid >> 5;
            int c4 = (tid & 31) * 4;
            *(float4*)(&Bs[k][c4]) = *(const float4*)(W + (size_t)(k0 + k) * HIDDEN + c4);
        }
        __syncthreads();

#pragma unroll
        for (int kk = 0; kk < BK; kk++) {
            float4 a0 = *(float4*)(&As[kk][rowBase]);
            float4 a1 = *(float4*)(&As[kk][rowBase + 4]);
            float4 b0 = *(float4*)(&Bs[kk][colBase]);
            float4 b1 = *(float4*)(&Bs[kk][colBase + 4]);
            float a[8] = {a0.x, a0.y, a0.z, a0.w, a1.x, a1.y, a1.z, a1.w};
            float b[8] = {b0.x, b0.y, b0.z, b0.w, b1.x, b1.y, b1.z, b1.w};
#pragma unroll
            for (int i = 0; i < 8; i++)
#pragma unroll
                for (int j = 0; j < 8; j++)
                    acc[i][j] = fmaf(a[i], b[j], acc[i][j]);
        }
        __syncthreads();
    }

#pragma unroll
    for (int i = 0; i < 8; i++) {
        int gr = blockRow + rowBase + i;
        if (gr < N_NODES) {
            __half2 hpack[4];
            hpack[0] = __floats2half2_rn(acc[i][0], acc[i][1]);
            hpack[1] = __floats2half2_rn(acc[i][2], acc[i][3]);
            hpack[2] = __floats2half2_rn(acc[i][4], acc[i][5]);
            hpack[3] = __floats2half2_rn(acc[i][6], acc[i][7]);
            *(uint4*)(g_h1h + (size_t)gr * HIDDEN + colBase) = *(uint4*)hpack;
        }
    }
}

// ---------------------------------------------------------------------------
// Macro: accumulate one fp16 row (uint4 = 8 halves) scaled by n into a[8]
// ---------------------------------------------------------------------------
#define ACC_ROW(r_, n_)                                                        \
    do {                                                                       \
        float2 f_;                                                             \
        f_ = __half22float2(*(__half2*)&(r_).x);                               \
        a[0] = fmaf(f_.x, (n_), a[0]); a[1] = fmaf(f_.y, (n_), a[1]);          \
        f_ = __half22float2(*(__half2*)&(r_).y);                               \
        a[2] = fmaf(f_.x, (n_), a[2]); a[3] = fmaf(f_.y, (n_), a[3]);          \
        f_ = __half22float2(*(__half2*)&(r_).z);                               \
        a[4] = fmaf(f_.x, (n_), a[4]); a[5] = fmaf(f_.y, (n_), a[5]);          \
        f_ = __half22float2(*(__half2*)&(r_).w);                               \
        a[6] = fmaf(f_.x, (n_), a[6]); a[7] = fmaf(f_.y, (n_), a[7]);          \
    } while (0)

#define GATHER2(off_)                                                          \
    do {                                                                       \
        int2 e_ = g_csr[i + (off_) + half];                                    \
        uint4 r_ = *(const uint4*)(g_h1h + (size_t)e_.x * HIDDEN + colOff);    \
        float n_ = __int_as_float(e_.y);                                       \
        ACC_ROW(r_, n_);                                                       \
    } while (0)

// ---------------------------------------------------------------------------
// K_agg1: fused layer-1 aggregation + epilogue. One warp per node,
// 2 edges per slot (half-warps), 16-edge unroll = 8 LDG.128 in flight/lane.
// ---------------------------------------------------------------------------
__global__ __launch_bounds__(256) void k_agg1(const float* __restrict__ b1,
                                              const float* __restrict__ W2,
                                              const float* __restrict__ b2,
                                              float* __restrict__ out) {
    int node = (blockIdx.x * blockDim.x + threadIdx.x) >> 5;
    int lane = threadIdx.x & 31;
    if (node >= N_NODES) return;

    const int half = lane >> 4;              // 0 or 1
    const int l16  = lane & 15;              // 0..15
    const size_t colOff = (size_t)l16 * 8;   // 8 halves per lane

    int beg = g_row[node];
    int end = beg + g_cnt[node];

    float a[8];
#pragma unroll
    for (int r = 0; r < 8; r++) a[r] = 0.f;

    int i = beg;
    for (; i + 15 < end; i += 16) {
        GATHER2(0); GATHER2(2); GATHER2(4); GATHER2(6);
        GATHER2(8); GATHER2(10); GATHER2(12); GATHER2(14);
    }
    for (; i + 7 < end; i += 8) {
        GATHER2(0); GATHER2(2); GATHER2(4); GATHER2(6);
    }
    for (; i + 3 < end; i += 4) {
        GATHER2(0); GATHER2(2);
    }
    for (; i + 1 < end; i += 2) {
        GATHER2(0);
    }
    if (i < end && half == 0) {
        int2 e0 = g_csr[i];
        uint4 r0 = *(const uint4*)(g_h1h + (size_t)e0.x * HIDDEN + colOff);
        float n0 = __int_as_float(e0.y);
        ACC_ROW(r0, n0);
    }

    // fold the two half-warps
#pragma unroll
    for (int r = 0; r < 8; r++)
        a[r] += __shfl_xor_sync(0xFFFFFFFFu, a[r], 16);

    float di = g_dinv[node];
    float d2 = di * di;

    uint4 sr = *(const uint4*)(g_h1h + (size_t)node * HIDDEN + colOff);
    float s[8];
    {
        float2 f;
        f = __half22float2(*(__half2*)&sr.x); s[0] = f.x; s[1] = f.y;
        f = __half22float2(*(__half2*)&sr.y); s[2] = f.x; s[3] = f.y;
        f = __half22float2(*(__half2*)&sr.z); s[4] = f.x; s[5] = f.y;
        f = __half22float2(*(__half2*)&sr.w); s[6] = f.x; s[7] = f.y;
    }
    float4 bb0 = *(const float4*)(b1 + colOff);
    float4 bb1 = *(const float4*)(b1 + colOff + 4);
    float4 w0  = *(const float4*)(W2 + colOff);
    float4 w1  = *(const float4*)(W2 + colOff + 4);
    float bbv[8] = {bb0.x, bb0.y, bb0.z, bb0.w, bb1.x, bb1.y, bb1.z, bb1.w};
    float wv [8] = {w0.x,  w0.y,  w0.z,  w0.w,  w1.x,  w1.y,  w1.z,  w1.w};

    float sum = 0.f;
#pragma unroll
    for (int r = 0; r < 8; r++) {
        float t = fmaxf(fmaf(s[r], d2, a[r]) + bbv[r], 0.0f);
        sum = fmaf(t, wv[r], sum);
    }
#pragma unroll
    for (int off = 8; off > 0; off >>= 1)
        sum += __shfl_xor_sync(0xFFFFFFFFu, sum, off);

    if (lane == 0) {
        g_h2[node] = sum;
        out[node]  = fmaf(sum, d2, b2[0]);  // layer-2 self-loop + bias
    }
}

// ---------------------------------------------------------------------------
// K_agg2: layer-2 gather. 8 lanes per node (4 nodes per warp).
// ---------------------------------------------------------------------------
__global__ __launch_bounds__(256) void k_agg2(float* __restrict__ out) {
    int gwarp = (blockIdx.x * blockDim.x + threadIdx.x) >> 5;
    int lane  = threadIdx.x & 31;
    int sub   = lane >> 3;     // 0..3
    int l8    = lane & 7;      // 0..7
    int node  = gwarp * 4 + sub;
    if (node >= N_NODES) return;

    int beg = g_row[node];
    int end = beg + g_cnt[node];

    float sum = 0.f;
    for (int i = beg + l8; i < end; i += 8) {
        int2 e = g_csr[i];
        sum = fmaf(g_h2[e.x], __int_as_float(e.y), sum);
    }

#pragma unroll
    for (int off = 4; off > 0; off >>= 1)
        sum += __shfl_xor_sync(0xFFFFFFFFu, sum, off);

    if (l8 == 0) out[node] += sum;
}

// ---------------------------------------------------------------------------
// Launch. GEMM on a forked side stream overlaps the CSR build chain.
// ---------------------------------------------------------------------------
extern "C" void kernel_launch(void* const* d_in, const int* in_sizes, int n_in,
                              void* d_out, int out_size) {
    const float* x  = (const float*)d_in[0];
    const void*  ei = d_in[1];
    const float* W1 = (const float*)d_in[2];
    const float* b1 = (const float*)d_in[3];
    const float* W2 = (const float*)d_in[4];
    const float* b2 = (const float*)d_in[5];
    float*       out = (float*)d_out;

    static cudaStream_t s2 = nullptr;
    static cudaEvent_t  evFork = nullptr, evJoin = nullptr;
    if (s2 == nullptr) {
        cudaStreamCreateWithFlags(&s2, cudaStreamNonBlocking);
        cudaEventCreateWithFlags(&evFork, cudaEventDisableTiming);
        cudaEventCreateWithFlags(&evJoin, cudaEventDisableTiming);
    }

    const int T = 256;

    // Fork: GEMM on side stream (depends only on x, W1)
    cudaEventRecord(evFork, 0);
    cudaStreamWaitEvent(s2, evFork, 0);
    k_gemm1<<<(N_NODES + BM - 1) / BM, 256, 0, s2>>>(x, W1);
    cudaEventRecord(evJoin, s2);

    // CSR build chain on main stream
    k_prep <<<(N_NODES + T - 1) / T, T>>>(ei);
    k_count<<<(N_EDGES + T - 1) / T, T>>>(ei);
    k_scan1<<<SCAN_B, SCAN_T>>>();
    k_scan3<<<SCAN_B, SCAN_T>>>();
    k_fill <<<(N_EDGES + T - 1) / T, T>>>(ei);

    // Join: aggregation needs both CSR and h1
    cudaStreamWaitEvent(0, evJoin, 0);
    {
        long long blocks = ((long long)N_NODES * 32 + T - 1) / T;
        k_agg1<<<(unsigned)blocks, T>>>(b1, W2, b2, out);
    }
    {
        long long blocks = ((long long)N_NODES * 8 + T - 1) / T;
        k_agg2<<<(unsigned)blocks, T>>>(out);
    }
}

// round 15
// speedup vs baseline: 1.8213x; 1.0885x over previous
#include <cuda_runtime.h>
#include <cuda_fp16.h>
#include <stdint.h>

// Problem constants (fixed by the dataset)
#define N_NODES 50000
#define N_EDGES 800000
#define D_FEAT  128
#define HIDDEN  128

// Padded bucket capacity per node. Degrees are Poisson(16); P(deg > 128)
// is ~1e-80. Writes are guarded, loop bounds clamped.
#define CAP 128

// Scratch (static device globals — no allocation allowed)
__device__ float  g_dinv[N_NODES];
__device__ __half g_h1h[(size_t)N_NODES * HIDDEN];    // x @ W1 (fp16)
__device__ float  g_h2s[N_NODES];                     // h2 * dinv (for layer-2 gather)
__device__ int    g_cursor[N_NODES];                  // degree counter / cursor
__device__ int    g_bucket[(size_t)N_NODES * CAP];    // src per slot
__device__ int    g_is64;

// ---------------------------------------------------------------------------
// Edge fetch helper (dtype decided by runtime probe)
// ---------------------------------------------------------------------------
__device__ __forceinline__ void load_edge(const void* ei, int i, int& s, int& d) {
    if (g_is64) {
        const long long* p = (const long long*)ei;
        s = (int)p[i];
        d = (int)p[i + N_EDGES];
    } else {
        const int* p = (const int*)ei;
        s = p[i];
        d = p[i + N_EDGES];
    }
    s = min(max(s, 0), N_NODES - 1);
    d = min(max(d, 0), N_NODES - 1);
}

// ---------------------------------------------------------------------------
// K_prep: zero cursors; thread 0 probes edge dtype.
// ---------------------------------------------------------------------------
__global__ void k_prep(const void* __restrict__ ei) {
    int i = blockIdx.x * blockDim.x + threadIdx.x;
    if (i < N_NODES) g_cursor[i] = 0;
    if (i == 0) {
        const long long* p = (const long long*)ei;
        int ok64 = 1;
        for (int k = 0; k < 16; k++) {
            long long v = p[k];
            if (v < 0 || v >= N_NODES) { ok64 = 0; break; }
        }
        g_is64 = ok64;
    }
}

// ---------------------------------------------------------------------------
// K_fill: single pass — bucket fill + degree count (cursor). No scan needed.
// ---------------------------------------------------------------------------
__global__ void k_fill(const void* __restrict__ ei) {
    int e = blockIdx.x * blockDim.x + threadIdx.x;
    if (e < N_EDGES) {
        int src, dst;
        load_edge(ei, e, src, dst);
        int pos = atomicAdd(&g_cursor[dst], 1);
        if (pos < CAP)
            g_bucket[(size_t)dst * CAP + pos] = src;
    }
}

// ---------------------------------------------------------------------------
// K_dinv: dinv = rsqrt(1 + degree)
// ---------------------------------------------------------------------------
__global__ void k_dinv() {
    int i = blockIdx.x * blockDim.x + threadIdx.x;
    if (i < N_NODES) g_dinv[i] = rsqrtf((float)(1 + g_cursor[i]));
}

// ---------------------------------------------------------------------------
// K3: h1 = x @ W1.  BM=128, BN=128, BK=8, 256 threads, 8x8 per-thread tile.
// Epilogue writes fp16. Forked stream, overlaps the bucket build.
// ---------------------------------------------------------------------------
#define BM 128
#define BN 128
#define BK 8

__global__ __launch_bounds__(256) void k_gemm1(const float* __restrict__ x,
                                               const float* __restrict__ W) {
    __shared__ float As[BK][BM];
    __shared__ float Bs[BK][BN];

    const int tid = threadIdx.x;
    const int blockRow = blockIdx.x * BM;
    const int rowBase = (tid >> 4) * 8;
    const int colBase = (tid & 15) * 8;

    float acc[8][8];
#pragma unroll
    for (int i = 0; i < 8; i++)
#pragma unroll
        for (int j = 0; j < 8; j++) acc[i][j] = 0.0f;

    for (int k0 = 0; k0 < D_FEAT; k0 += BK) {
        {
            int r  = tid >> 1;
            int kv = (tid & 1) * 4;
            int gr = blockRow + r;
            float4 v = make_float4(0.f, 0.f, 0.f, 0.f);
            if (gr < N_NODES)
                v = *(const float4*)(x + (size_t)gr * D_FEAT + k0 + kv);
            As[kv + 0][r] = v.x;
            As[kv + 1][r] = v.y;
            As[kv + 2][r] = v.z;
            As[kv + 3][r] = v.w;
        }
        {
            int k  = tid >> 5;
            int c4 = (tid & 31) * 4;
            *(float4*)(&Bs[k][c4]) = *(const float4*)(W + (size_t)(k0 + k) * HIDDEN + c4);
        }
        __syncthreads();

#pragma unroll
        for (int kk = 0; kk < BK; kk++) {
            float4 a0 = *(float4*)(&As[kk][rowBase]);
            float4 a1 = *(float4*)(&As[kk][rowBase + 4]);
            float4 b0 = *(float4*)(&Bs[kk][colBase]);
            float4 b1 = *(float4*)(&Bs[kk][colBase + 4]);
            float a[8] = {a0.x, a0.y, a0.z, a0.w, a1.x, a1.y, a1.z, a1.w};
            float b[8] = {b0.x, b0.y, b0.z, b0.w, b1.x, b1.y, b1.z, b1.w};
#pragma unroll
            for (int i = 0; i < 8; i++)
#pragma unroll
                for (int j = 0; j < 8; j++)
                    acc[i][j] = fmaf(a[i], b[j], acc[i][j]);
        }
        __syncthreads();
    }

#pragma unroll
    for (int i = 0; i < 8; i++) {
        int gr = blockRow + rowBase + i;
        if (gr < N_NODES) {
            __half2 hpack[4];
            hpack[0] = __floats2half2_rn(acc[i][0], acc[i][1]);
            hpack[1] = __floats2half2_rn(acc[i][2], acc[i][3]);
            hpack[2] = __floats2half2_rn(acc[i][4], acc[i][5]);
            hpack[3] = __floats2half2_rn(acc[i][6], acc[i][7]);
            *(uint4*)(g_h1h + (size_t)gr * HIDDEN + colBase) = *(uint4*)hpack;
        }
    }
}

// ---------------------------------------------------------------------------
// Macro: accumulate one fp16 row (uint4 = 8 halves) scaled by n into a[8]
// ---------------------------------------------------------------------------
#define ACC_ROW(r_, n_)                                                        \
    do {                                                                       \
        float2 f_;                                                             \
        f_ = __half22float2(*(__half2*)&(r_).x);                               \
        a[0] = fmaf(f_.x, (n_), a[0]); a[1] = fmaf(f_.y, (n_), a[1]);          \
        f_ = __half22float2(*(__half2*)&(r_).y);                               \
        a[2] = fmaf(f_.x, (n_), a[2]); a[3] = fmaf(f_.y, (n_), a[3]);          \
        f_ = __half22float2(*(__half2*)&(r_).z);                               \
        a[4] = fmaf(f_.x, (n_), a[4]); a[5] = fmaf(f_.y, (n_), a[5]);          \
        f_ = __half22float2(*(__half2*)&(r_).w);                               \
        a[6] = fmaf(f_.x, (n_), a[6]); a[7] = fmaf(f_.y, (n_), a[7]);          \
    } while (0)

// Gather one edge per half-warp: src index (broadcast), dinv[src] (broadcast),
// then the fp16 row slice. Weight is dinv[src] only — dinv[node] is factored
// out and applied once after the loop.
#define GATHER2(off_)                                                          \
    do {                                                                       \
        int s_ = g_bucket[nodeBase + i + (off_) + half];                       \
        float n_ = g_dinv[s_];                                                 \
        uint4 r_ = *(const uint4*)(g_h1h + (size_t)s_ * HIDDEN + colOff);      \
        ACC_ROW(r_, n_);                                                       \
    } while (0)

// ---------------------------------------------------------------------------
// K_agg1: fused layer-1 aggregation + epilogue. One warp per node,
// 2 edges per slot (half-warps), 16-edge unroll.
//   pre-act col r = dinv_n * a_r + h1[n]_r * dinv_n^2 + b1_r
//   h2s[n] = h2[n] * dinv_n;  out[n] = h2[n]*dinv_n^2 + b2
// ---------------------------------------------------------------------------
__global__ __launch_bounds__(256) void k_agg1(const float* __restrict__ b1,
                                              const float* __restrict__ W2,
                                              const float* __restrict__ b2,
                                              float* __restrict__ out) {
    int node = (blockIdx.x * blockDim.x + threadIdx.x) >> 5;
    int lane = threadIdx.x & 31;
    if (node >= N_NODES) return;

    const int half = lane >> 4;              // 0 or 1
    const int l16  = lane & 15;              // 0..15
    const size_t colOff = (size_t)l16 * 8;   // 8 halves per lane
    const size_t nodeBase = (size_t)node * CAP;

    int cnt = min(g_cursor[node], CAP);
    int end = cnt;

    float a[8];
#pragma unroll
    for (int r = 0; r < 8; r++) a[r] = 0.f;

    int i = 0;
    for (; i + 15 < end; i += 16) {
        GATHER2(0); GATHER2(2); GATHER2(4); GATHER2(6);
        GATHER2(8); GATHER2(10); GATHER2(12); GATHER2(14);
    }
    for (; i + 7 < end; i += 8) {
        GATHER2(0); GATHER2(2); GATHER2(4); GATHER2(6);
    }
    for (; i + 3 < end; i += 4) {
        GATHER2(0); GATHER2(2);
    }
    for (; i + 1 < end; i += 2) {
        GATHER2(0);
    }
    if (i < end && half == 0) {
        int s0 = g_bucket[nodeBase + i];
        float n0 = g_dinv[s0];
        uint4 r0 = *(const uint4*)(g_h1h + (size_t)s0 * HIDDEN + colOff);
        ACC_ROW(r0, n0);
    }

    // fold the two half-warps
#pragma unroll
    for (int r = 0; r < 8; r++)
        a[r] += __shfl_xor_sync(0xFFFFFFFFu, a[r], 16);

    float dn = g_dinv[node];
    float d2 = dn * dn;

    uint4 sr = *(const uint4*)(g_h1h + (size_t)node * HIDDEN + colOff);
    float s[8];
    {
        float2 f;
        f = __half22float2(*(__half2*)&sr.x); s[0] = f.x; s[1] = f.y;
        f = __half22float2(*(__half2*)&sr.y); s[2] = f.x; s[3] = f.y;
        f = __half22float2(*(__half2*)&sr.z); s[4] = f.x; s[5] = f.y;
        f = __half22float2(*(__half2*)&sr.w); s[6] = f.x; s[7] = f.y;
    }
    float4 bb0 = *(const float4*)(b1 + colOff);
    float4 bb1 = *(const float4*)(b1 + colOff + 4);
    float4 w0  = *(const float4*)(W2 + colOff);
    float4 w1  = *(const float4*)(W2 + colOff + 4);
    float bbv[8] = {bb0.x, bb0.y, bb0.z, bb0.w, bb1.x, bb1.y, bb1.z, bb1.w};
    float wv [8] = {w0.x,  w0.y,  w0.z,  w0.w,  w1.x,  w1.y,  w1.z,  w1.w};

    float sum = 0.f;
#pragma unroll
    for (int r = 0; r < 8; r++) {
        // dinv_n * a_r (edges) + s_r * dinv_n^2 (self) + b1_r
        float t = fmaxf(fmaf(s[r], d2, dn * a[r]) + bbv[r], 0.0f);
        sum = fmaf(t, wv[r], sum);
    }
#pragma unroll
    for (int off = 8; off > 0; off >>= 1)
        sum += __shfl_xor_sync(0xFFFFFFFFu, sum, off);

    if (lane == 0) {
        g_h2s[node] = sum * dn;             // pre-scaled for layer-2 gather
        out[node]   = fmaf(sum, d2, b2[0]); // layer-2 self-loop + bias
    }
}

// ---------------------------------------------------------------------------
// K_agg2: layer-2 gather. 8 lanes per node (4 nodes per warp).
//   out[n] += dinv_n * sum_in h2s[src]
// ---------------------------------------------------------------------------
__global__ __launch_bounds__(256) void k_agg2(float* __restrict__ out) {
    int gwarp = (blockIdx.x * blockDim.x + threadIdx.x) >> 5;
    int lane  = threadIdx.x & 31;
    int sub   = lane >> 3;     // 0..3
    int l8    = lane & 7;      // 0..7
    int node  = gwarp * 4 + sub;
    if (node >= N_NODES) return;

    const size_t nodeBase = (size_t)node * CAP;
    int cnt = min(g_cursor[node], CAP);

    float sum = 0.f;
    for (int i = l8; i < cnt; i += 8)
        sum += g_h2s[g_bucket[nodeBase + i]];

#pragma unroll
    for (int off = 4; off > 0; off >>= 1)
        sum += __shfl_xor_sync(0xFFFFFFFFu, sum, off);

    if (l8 == 0) out[node] += g_dinv[node] * sum;
}

// ---------------------------------------------------------------------------
// Launch. GEMM on a forked side stream overlaps the bucket build chain
// (prep -> fill -> dinv). No count, no scan.
// ---------------------------------------------------------------------------
extern "C" void kernel_launch(void* const* d_in, const int* in_sizes, int n_in,
                              void* d_out, int out_size) {
    const float* x  = (const float*)d_in[0];
    const void*  ei = d_in[1];
    const float* W1 = (const float*)d_in[2];
    const float* b1 = (const float*)d_in[3];
    const float* W2 = (const float*)d_in[4];
    const float* b2 = (const float*)d_in[5];
    float*       out = (float*)d_out;

    static cudaStream_t s2 = nullptr;
    static cudaEvent_t  evFork = nullptr, evJoin = nullptr;
    if (s2 == nullptr) {
        cudaStreamCreateWithFlags(&s2, cudaStreamNonBlocking);
        cudaEventCreateWithFlags(&evFork, cudaEventDisableTiming);
        cudaEventCreateWithFlags(&evJoin, cudaEventDisableTiming);
    }

    const int T = 256;

    // Fork: GEMM on side stream (depends only on x, W1)
    cudaEventRecord(evFork, 0);
    cudaStreamWaitEvent(s2, evFork, 0);
    k_gemm1<<<(N_NODES + BM - 1) / BM, 256, 0, s2>>>(x, W1);
    cudaEventRecord(evJoin, s2);

    // Bucket build chain on main stream
    k_prep<<<(N_NODES + T - 1) / T, T>>>(ei);
    k_fill<<<(N_EDGES + T - 1) / T, T>>>(ei);
    k_dinv<<<(N_NODES + T - 1) / T, T>>>();

    // Join: aggregation needs both buckets and h1
    cudaStreamWaitEvent(0, evJoin, 0);
    {
        long long blocks = ((long long)N_NODES * 32 + T - 1) / T;
        k_agg1<<<(unsigned)blocks, T>>>(b1, W2, b2, out);
    }
    {
        long long blocks = ((long long)N_NODES * 8 + T - 1) / T;
        k_agg2<<<(unsigned)blocks, T>>>(out);
    }
}

// round 17
// speedup vs baseline: 1.8769x; 1.0305x over previous
#include <cuda_runtime.h>
#include <cuda_fp16.h>
#include <stdint.h>

// Problem constants (fixed by the dataset)
#define N_NODES 50000
#define N_EDGES 800000
#define D_FEAT  128
#define HIDDEN  128

// Padded bucket capacity per node (Poisson(16) degrees; guarded writes).
#define CAP 128

// Scratch (static device globals — no allocation allowed)
__device__ float  g_dinv[N_NODES];
__device__ __half g_h1h[(size_t)N_NODES * HIDDEN];    // x @ W1 (fp16)
__device__ float  g_h2s[N_NODES];                     // h2 * dinv (for layer-2 gather)
__device__ int    g_cursor[N_NODES];                  // degree counter / cursor
__device__ int    g_bucket[(size_t)N_NODES * CAP];    // src per slot
__device__ int    g_is64;

// ---------------------------------------------------------------------------
// Edge fetch helper (dtype decided by runtime probe)
// ---------------------------------------------------------------------------
__device__ __forceinline__ void load_edge(const void* ei, int i, int& s, int& d) {
    if (g_is64) {
        const long long* p = (const long long*)ei;
        s = (int)p[i];
        d = (int)p[i + N_EDGES];
    } else {
        const int* p = (const int*)ei;
        s = p[i];
        d = p[i + N_EDGES];
    }
    s = min(max(s, 0), N_NODES - 1);
    d = min(max(d, 0), N_NODES - 1);
}

// ---------------------------------------------------------------------------
// K_probe: 1 thread — edge dtype detection.
// ---------------------------------------------------------------------------
__global__ void k_probe(const void* __restrict__ ei) {
    const long long* p = (const long long*)ei;
    int ok64 = 1;
    for (int k = 0; k < 16; k++) {
        long long v = p[k];
        if (v < 0 || v >= N_NODES) { ok64 = 0; break; }
    }
    g_is64 = ok64;
}

// ---------------------------------------------------------------------------
// K_fill: single pass — bucket fill + degree count (cursor). No scan needed.
// ---------------------------------------------------------------------------
__global__ void k_fill(const void* __restrict__ ei) {
    int e = blockIdx.x * blockDim.x + threadIdx.x;
    if (e < N_EDGES) {
        int src, dst;
        load_edge(ei, e, src, dst);
        int pos = atomicAdd(&g_cursor[dst], 1);
        if (pos < CAP)
            g_bucket[(size_t)dst * CAP + pos] = src;
    }
}

// ---------------------------------------------------------------------------
// K_dinv: dinv = rsqrt(1 + degree)
// ---------------------------------------------------------------------------
__global__ void k_dinv() {
    int i = blockIdx.x * blockDim.x + threadIdx.x;
    if (i < N_NODES) g_dinv[i] = rsqrtf((float)(1 + g_cursor[i]));
}

// ---------------------------------------------------------------------------
// K3: h1 = x @ W1.  BM=128, BN=128, BK=8, 256 threads, 8x8 per-thread tile.
// Epilogue writes fp16. Forked stream, overlaps the bucket build.
// ---------------------------------------------------------------------------
#define BM 128
#define BN 128
#define BK 8

__global__ __launch_bounds__(256) void k_gemm1(const float* __restrict__ x,
                                               const float* __restrict__ W) {
    __shared__ float As[BK][BM];
    __shared__ float Bs[BK][BN];

    const int tid = threadIdx.x;
    const int blockRow = blockIdx.x * BM;
    const int rowBase = (tid >> 4) * 8;
    const int colBase = (tid & 15) * 8;

    float acc[8][8];
#pragma unroll
    for (int i = 0; i < 8; i++)
#pragma unroll
        for (int j = 0; j < 8; j++) acc[i][j] = 0.0f;

    for (int k0 = 0; k0 < D_FEAT; k0 += BK) {
        {
            int r  = tid >> 1;
            int kv = (tid & 1) * 4;
            int gr = blockRow + r;
            float4 v = make_float4(0.f, 0.f, 0.f, 0.f);
            if (gr < N_NODES)
                v = *(const float4*)(x + (size_t)gr * D_FEAT + k0 + kv);
            As[kv + 0][r] = v.x;
            As[kv + 1][r] = v.y;
            As[kv + 2][r] = v.z;
            As[kv + 3][r] = v.w;
        }
        {
            int k  = tid >> 5;
            int c4 = (tid & 31) * 4;
            *(float4*)(&Bs[k][c4]) = *(const float4*)(W + (size_t)(k0 + k) * HIDDEN + c4);
        }
        __syncthreads();

#pragma unroll
        for (int kk = 0; kk < BK; kk++) {
            float4 a0 = *(float4*)(&As[kk][rowBase]);
            float4 a1 = *(float4*)(&As[kk][rowBase + 4]);
            float4 b0 = *(float4*)(&Bs[kk][colBase]);
            float4 b1 = *(float4*)(&Bs[kk][colBase + 4]);
            float a[8] = {a0.x, a0.y, a0.z, a0.w, a1.x, a1.y, a1.z, a1.w};
            float b[8] = {b0.x, b0.y, b0.z, b0.w, b1.x, b1.y, b1.z, b1.w};
#pragma unroll
            for (int i = 0; i < 8; i++)
#pragma unroll
                for (int j = 0; j < 8; j++)
                    acc[i][j] = fmaf(a[i], b[j], acc[i][j]);
        }
        __syncthreads();
    }

#pragma unroll
    for (int i = 0; i < 8; i++) {
        int gr = blockRow + rowBase + i;
        if (gr < N_NODES) {
            __half2 hpack[4];
            hpack[0] = __floats2half2_rn(acc[i][0], acc[i][1]);
            hpack[1] = __floats2half2_rn(acc[i][2], acc[i][3]);
            hpack[2] = __floats2half2_rn(acc[i][4], acc[i][5]);
            hpack[3] = __floats2half2_rn(acc[i][6], acc[i][7]);
            *(uint4*)(g_h1h + (size_t)gr * HIDDEN + colBase) = *(uint4*)hpack;
        }
    }
}

// ---------------------------------------------------------------------------
// K_agg1: fused layer-1 aggregation + epilogue. One warp per node.
// Index batching: one coalesced LDG fetches up to 32 srcs; one gathered LDG
// fetches their dinv; shfl broadcasts per edge. Row loads (32 lanes x uint2
// = 256B) are then fully independent -> max MLP.
//   col c (= lane*4 + r): pre-act = dn*a_r + h1[n]_c*dn^2 + b1_c
//   h2s[n] = h2[n]*dn;  out[n] = h2[n]*dn^2 + b2
// ---------------------------------------------------------------------------
#define EDGE1(e_)                                                              \
    do {                                                                       \
        int   se_ = __shfl_sync(0xFFFFFFFFu, sv, (e_));                        \
        float ne_ = __shfl_sync(0xFFFFFFFFu, nv, (e_));                        \
        uint2 r_ = *(const uint2*)(g_h1h + (size_t)se_ * HIDDEN + (lane << 2));\
        float2 p_ = __half22float2(*(__half2*)&r_.x);                          \
        float2 q_ = __half22float2(*(__half2*)&r_.y);                          \
        a0 = fmaf(p_.x, ne_, a0); a1 = fmaf(p_.y, ne_, a1);                    \
        a2 = fmaf(q_.x, ne_, a2); a3 = fmaf(q_.y, ne_, a3);                    \
    } while (0)

__global__ __launch_bounds__(256) void k_agg1(const float* __restrict__ b1,
                                              const float* __restrict__ W2,
                                              const float* __restrict__ b2,
                                              float* __restrict__ out) {
    int node = (blockIdx.x * blockDim.x + threadIdx.x) >> 5;
    int lane = threadIdx.x & 31;
    if (node >= N_NODES) return;

    const size_t nodeBase = (size_t)node * CAP;
    int cnt = min(g_cursor[node], CAP);

    float a0 = 0.f, a1 = 0.f, a2 = 0.f, a3 = 0.f;

    for (int b = 0; b < cnt; b += 32) {
        int m = min(32, cnt - b);
        int sv = 0;
        float nv = 0.f;
        if (lane < m) {
            sv = g_bucket[nodeBase + b + lane];   // coalesced 32 srcs
            nv = g_dinv[sv];                      // gathered dinv, parallel
        }
        int e = 0;
        for (; e + 3 < m; e += 4) {
            EDGE1(e); EDGE1(e + 1); EDGE1(e + 2); EDGE1(e + 3);
        }
        for (; e < m; e++) EDGE1(e);
    }

    float dn = g_dinv[node];
    float d2 = dn * dn;

    // self row (fp16), bias, W2 — 4 cols per lane at lane*4
    uint2 sr = *(const uint2*)(g_h1h + (size_t)node * HIDDEN + (lane << 2));
    float2 sp = __half22float2(*(__half2*)&sr.x);
    float2 sq = __half22float2(*(__half2*)&sr.y);

    float4 bb = *(const float4*)(b1 + (lane << 2));
    float4 w  = *(const float4*)(W2 + (lane << 2));

    float t0 = fmaxf(fmaf(sp.x, d2, dn * a0) + bb.x, 0.0f);
    float t1 = fmaxf(fmaf(sp.y, d2, dn * a1) + bb.y, 0.0f);
    float t2 = fmaxf(fmaf(sq.x, d2, dn * a2) + bb.z, 0.0f);
    float t3 = fmaxf(fmaf(sq.y, d2, dn * a3) + bb.w, 0.0f);

    float sum = t0 * w.x + t1 * w.y + t2 * w.z + t3 * w.w;
#pragma unroll
    for (int off = 16; off > 0; off >>= 1)
        sum += __shfl_xor_sync(0xFFFFFFFFu, sum, off);

    if (lane == 0) {
        g_h2s[node] = sum * dn;             // pre-scaled for layer-2 gather
        out[node]   = fmaf(sum, d2, b2[0]); // layer-2 self-loop + bias
    }
}

// ---------------------------------------------------------------------------
// K_agg2: layer-2 gather. 8 lanes per node (4 nodes per warp).
//   out[n] += dinv_n * sum_in h2s[src]
// ---------------------------------------------------------------------------
__global__ __launch_bounds__(256) void k_agg2(float* __restrict__ out) {
    int gwarp = (blockIdx.x * blockDim.x + threadIdx.x) >> 5;
    int lane  = threadIdx.x & 31;
    int sub   = lane >> 3;     // 0..3
    int l8    = lane & 7;      // 0..7
    int node  = gwarp * 4 + sub;
    if (node >= N_NODES) return;

    const size_t nodeBase = (size_t)node * CAP;
    int cnt = min(g_cursor[node], CAP);

    float sum = 0.f;
    for (int i = l8; i < cnt; i += 8)
        sum += g_h2s[g_bucket[nodeBase + i]];

#pragma unroll
    for (int off = 4; off > 0; off >>= 1)
        sum += __shfl_xor_sync(0xFFFFFFFFu, sum, off);

    if (l8 == 0) out[node] += g_dinv[node] * sum;
}

// ---------------------------------------------------------------------------
// Launch. GEMM on a forked side stream overlaps the bucket build chain
// (memset -> probe -> fill -> dinv).
// ---------------------------------------------------------------------------
extern "C" void kernel_launch(void* const* d_in, const int* in_sizes, int n_in,
                              void* d_out, int out_size) {
    const float* x  = (const float*)d_in[0];
    const void*  ei = d_in[1];
    const float* W1 = (const float*)d_in[2];
    const float* b1 = (const float*)d_in[3];
    const float* W2 = (const float*)d_in[4];
    const float* b2 = (const float*)d_in[5];
    float*       out = (float*)d_out;

    static cudaStream_t s2 = nullptr;
    static cudaEvent_t  evFork = nullptr, evJoin = nullptr;
    static void* cursorAddr = nullptr;
    if (s2 == nullptr) {
        cudaStreamCreateWithFlags(&s2, cudaStreamNonBlocking);
        cudaEventCreateWithFlags(&evFork, cudaEventDisableTiming);
        cudaEventCreateWithFlags(&evJoin, cudaEventDisableTiming);
        cudaGetSymbolAddress(&cursorAddr, g_cursor);
    }

    const int T = 256;

    // Fork: GEMM on side stream (depends only on x, W1)
    cudaEventRecord(evFork, 0);
    cudaStreamWaitEvent(s2, evFork, 0);
    k_gemm1<<<(N_NODES + BM - 1) / BM, 256, 0, s2>>>(x, W1);
    cudaEventRecord(evJoin, s2);

    // Bucket build chain on main stream
    cudaMemsetAsync(cursorAddr, 0, N_NODES * sizeof(int), 0);
    k_probe<<<1, 1>>>(ei);
    k_fill<<<(N_EDGES + T - 1) / T, T>>>(ei);
    k_dinv<<<(N_NODES + T - 1) / T, T>>>();

    // Join: aggregation needs both buckets and h1
    cudaStreamWaitEvent(0, evJoin, 0);
    {
        long long blocks = ((long long)N_NODES * 32 + T - 1) / T;
        k_agg1<<<(unsigned)blocks, T>>>(b1, W2, b2, out);
    }
    {
        long long blocks = ((long long)N_NODES * 8 + T - 1) / T;
        k_agg2<<<(unsigned)blocks, T>>>(out);
    }
}